// round 15
// baseline (speedup 1.0000x reference)
#include <cuda_runtime.h>
#include <cuda_fp16.h>
#include <math.h>
#include <stdint.h>

// Problem constants (fixed by the dataset).
#define NN 10000
#define EE 160000

// ---------------- device scratch (no allocations allowed) ----------------
__device__ __align__(256) float g_hW   [NN * 1024];
__device__ __align__(256) float g_dfin [NN * 1024];
__device__ __align__(256) float g_lin512[NN * 512];
__device__ __align__(256) float g_h3   [NN * 128];
__device__ __align__(256) float g_z    [NN * 64];
__device__ __align__(256) float g_als  [NN * 2];
__device__ __align__(256) float g_ald  [NN * 2];
__device__ __align__(256) float g_sq   [NN];
__device__ __align__(256) float g_dinv [NN];
__device__ __align__(256) float g_mean [1024];
__device__ __align__(256) float g_mpart[8 * 1024];
__device__ __align__(256) float g_wv   [512 * 4];   // (src h0, src h1, dst h0, dst h1) per k
__device__ __align__(256) int   g_deg  [NN];
__device__ __align__(256) int   g_rowptr[NN + 1];
__device__ __align__(256) int   g_cursor[NN];
__device__ __align__(256) int   g_csrsrc[EE];
// fp16 2-term splits (primary + secondary to break aliasing in dec chain)
__device__ __align__(256) __half g_Xhi[NN * 1024];
__device__ __align__(256) __half g_Xlo[NN * 1024];
__device__ __align__(256) __half g_Yhi[NN * 512];
__device__ __align__(256) __half g_Ylo[NN * 512];
// fp16 2-term split of transposed weights (max 1024x512)
__device__ __align__(256) __half g_Wh[1 << 20];
__device__ __align__(256) __half g_Wl[1 << 20];

__device__ float g_zero_bias[1024];   // zero-initialized (bias-less layers)

__device__ __forceinline__ float leaky02(float x) { return x > 0.f ? x : 0.2f * x; }

__device__ __forceinline__ void split2(float v, __half& h, __half& l) {
    h = __float2half_rn(v);
    l = __float2half_rn(v - __half2float(h));
}

// ---------------- graph build ----------------
__global__ void k_zero_int(int* p, int n) {
    int i = blockIdx.x * blockDim.x + threadIdx.x;
    if (i < n) p[i] = 0;
}

__global__ void k_count(const int* __restrict__ dst, int* __restrict__ deg, int e) {
    int i = blockIdx.x * blockDim.x + threadIdx.x;
    if (i < e) atomicAdd(&deg[dst[i]], 1);
}

__global__ void k_scan(const int* __restrict__ deg, int* __restrict__ rowptr,
                       int* __restrict__ cursor, float* __restrict__ dinv, int n) {
    __shared__ int sh[1024];
    __shared__ int carry;
    int tid = threadIdx.x;
    if (tid == 0) carry = 0;
    __syncthreads();
    for (int base = 0; base < n; base += 1024) {
        int i = base + tid;
        int v = (i < n) ? deg[i] : 0;
        sh[tid] = v;
        __syncthreads();
        for (int off = 1; off < 1024; off <<= 1) {
            int t = (tid >= off) ? sh[tid - off] : 0;
            __syncthreads();
            sh[tid] += t;
            __syncthreads();
        }
        if (i < n) {
            rowptr[i] = carry + sh[tid] - v;   // exclusive
            cursor[i] = 0;
            dinv[i] = rsqrtf((float)(v + 1));
        }
        __syncthreads();
        if (tid == 0) carry += sh[1023];
        __syncthreads();
    }
    if (tid == 0) rowptr[n] = carry;
}

__global__ void k_fill(const int* __restrict__ src, const int* __restrict__ dst,
                       const int* __restrict__ rowptr, int* __restrict__ cursor,
                       int* __restrict__ csrsrc, int e) {
    int i = blockIdx.x * blockDim.x + threadIdx.x;
    if (i < e) {
        int d = dst[i];
        int p = atomicAdd(&cursor[d], 1);
        csrsrc[rowptr[d] + p] = src[i];
    }
}

// ---------------- fp32 GEMM (tiny layers; optional fp16-split output) --------
template <bool BIAS, bool RELU, bool SPLIT>
__global__ __launch_bounds__(256)
void k_sgemm(const float* __restrict__ A, const float* __restrict__ B,
             const float* __restrict__ bias, float* __restrict__ C,
             __half* __restrict__ Chi, __half* __restrict__ Clo,
             int M, int Ncol, int K) {
    const int BM = 128, BN = 128, BK = 8;
    __shared__ float As[BK][BM];
    __shared__ float Bs[BK][BN];
    int tid = threadIdx.x;
    int row0 = blockIdx.y * BM, col0 = blockIdx.x * BN;
    int tx = tid % 16, ty = tid / 16;
    float acc[8][8] = {};
    int aRow = tid >> 1, aCol = (tid & 1) * 4;
    int bRow = tid >> 5, bCol = (tid & 31) * 4;
    for (int k0 = 0; k0 < K; k0 += BK) {
        float4 av = make_float4(0, 0, 0, 0);
        if (row0 + aRow < M)
            av = *(const float4*)(A + (size_t)(row0 + aRow) * K + k0 + aCol);
        As[aCol + 0][aRow] = av.x; As[aCol + 1][aRow] = av.y;
        As[aCol + 2][aRow] = av.z; As[aCol + 3][aRow] = av.w;
        float4 bv = make_float4(0, 0, 0, 0);
        if (col0 + bCol < Ncol)
            bv = *(const float4*)(B + (size_t)(k0 + bRow) * Ncol + col0 + bCol);
        *(float4*)&Bs[bRow][bCol] = bv;
        __syncthreads();
#pragma unroll
        for (int k = 0; k < BK; k++) {
            float ar[8], br[8];
            *(float4*)ar       = *(float4*)&As[k][ty * 8];
            *(float4*)(ar + 4) = *(float4*)&As[k][ty * 8 + 4];
            *(float4*)br       = *(float4*)&Bs[k][tx * 8];
            *(float4*)(br + 4) = *(float4*)&Bs[k][tx * 8 + 4];
#pragma unroll
            for (int i = 0; i < 8; i++)
#pragma unroll
                for (int j = 0; j < 8; j++)
                    acc[i][j] = fmaf(ar[i], br[j], acc[i][j]);
        }
        __syncthreads();
    }
#pragma unroll
    for (int i = 0; i < 8; i++) {
        int r = row0 + ty * 8 + i;
        if (r >= M) continue;
#pragma unroll
        for (int j = 0; j < 8; j++) {
            int c = col0 + tx * 8 + j;
            if (c >= Ncol) continue;
            float v = acc[i][j];
            if (BIAS) v += bias[c];
            if (RELU) v = fmaxf(v, 0.f);
            if (SPLIT) {
                __half h, l;
                split2(v, h, l);
                Chi[(size_t)r * Ncol + c] = h;
                Clo[(size_t)r * Ncol + c] = l;
            } else {
                C[(size_t)r * Ncol + c] = v;
            }
        }
    }
}

// ---------------- fp16 2-term splits ----------------
__global__ void k_split(const float* __restrict__ x, __half* __restrict__ hi,
                        __half* __restrict__ lo, int n) {
    int i = blockIdx.x * blockDim.x + threadIdx.x;
    if (i < n) {
        __half h, l;
        split2(x[i], h, l);
        hi[i] = h; lo[i] = l;
    }
}

// W[K][N] row-major -> Wt_hi/lo[N][K] (transposed) fp16 split
__global__ void k_wsplit(const float* __restrict__ W, __half* __restrict__ hi,
                         __half* __restrict__ lo, int Kd, int Nd) {
    int i = blockIdx.x * blockDim.x + threadIdx.x;
    if (i < Kd * Nd) {
        int nr = i / Kd, kr = i % Kd;
        __half h, l;
        split2(W[(size_t)kr * Nd + nr], h, l);
        hi[i] = h; lo[i] = l;
    }
}

// ---------------- shared mma/ldmatrix/cp.async helpers ----------------
__device__ __forceinline__ void mma_fp16(float* c, const unsigned* a, const unsigned* b) {
    asm volatile(
        "mma.sync.aligned.m16n8k16.row.col.f32.f16.f16.f32 "
        "{%0,%1,%2,%3}, {%4,%5,%6,%7}, {%8,%9}, {%0,%1,%2,%3};\n"
        : "+f"(c[0]), "+f"(c[1]), "+f"(c[2]), "+f"(c[3])
        : "r"(a[0]), "r"(a[1]), "r"(a[2]), "r"(a[3]), "r"(b[0]), "r"(b[1]));
}

__device__ __forceinline__ void ldsm4(unsigned* r, uint32_t addr) {
    asm volatile("ldmatrix.sync.aligned.m8n8.x4.shared.b16 {%0,%1,%2,%3}, [%4];"
                 : "=r"(r[0]), "=r"(r[1]), "=r"(r[2]), "=r"(r[3]) : "r"(addr));
}
__device__ __forceinline__ void ldsm2(unsigned* r, uint32_t addr) {
    asm volatile("ldmatrix.sync.aligned.m8n8.x2.shared.b16 {%0,%1}, [%2];"
                 : "=r"(r[0]), "=r"(r[1]) : "r"(addr));
}

// .cg: bypass L1 (streamed once, no reuse)
__device__ __forceinline__ void cpasync16(uint32_t dst, const void* src, int srcbytes) {
    asm volatile("cp.async.cg.shared.global [%0], [%1], 16, %2;"
                 :: "r"(dst), "l"(src), "r"(srcbytes) : "memory");
}
#define CP_COMMIT() asm volatile("cp.async.commit_group;" ::: "memory")
#define CP_WAIT1()  asm volatile("cp.async.wait_group 1;" ::: "memory")
#define CP_WAIT0()  asm volatile("cp.async.wait_group 0;" ::: "memory")

#define STAGE_BYTES 32768

// ---------------- fp16-split dense GEMM: C = A @ Wt^T (+bias)(+relu) ----------
template <bool RELU, bool SPLIT>
__global__ __launch_bounds__(256, 2)
void k_hgemm(const __half* __restrict__ Ahi, const __half* __restrict__ Alo,
             const __half* __restrict__ Bhi_g, const __half* __restrict__ Blo_g,
             const float* __restrict__ bias, float* __restrict__ C,
             __half* __restrict__ Chi, __half* __restrict__ Clo,
             int M, int Ncol, int K) {
    int bi = blockIdx.y, bj = blockIdx.x;
    const int KC = 32;
    int NCH = K / KC;
    extern __shared__ __align__(1024) char dsm[];
    int tid = threadIdx.x;
    int lane = tid & 31, warp = tid >> 5;
    int wm = warp >> 2, wn = warp & 3;
    int row0 = bi * 128, col0 = bj * 128;

    float acc[16][4] = {};

    int lrow0 = tid >> 2, lseg0 = tid & 3;
    int s0 = lseg0 ^ ((lrow0 >> 1) & 3);
    int s1 = lseg0 ^ (((lrow0 + 64) >> 1) & 3);
    uint32_t sbase = (uint32_t)__cvta_generic_to_shared(dsm);
    uint32_t d0 = (uint32_t)(lrow0 * 64 + s0 * 16);
    uint32_t d1 = (uint32_t)((lrow0 + 64) * 64 + s1 * 16);

    int ga0 = row0 + lrow0, ga1 = ga0 + 64;
    int gb0 = col0 + lrow0, gb1 = gb0 + 64;
    int pa0 = (ga0 < M) ? 16 : 0, pa1 = (ga1 < M) ? 16 : 0;
    int pb0 = (gb0 < Ncol) ? 16 : 0, pb1 = (gb1 < Ncol) ? 16 : 0;
    int ga0c = (ga0 < M) ? ga0 : 0, ga1c = (ga1 < M) ? ga1 : 0;
    int gb0c = (gb0 < Ncol) ? gb0 : 0, gb1c = (gb1 < Ncol) ? gb1 : 0;
    const char* pA0 = (const char*)(Ahi + (size_t)ga0c * K + lseg0 * 8);
    const char* pA1 = (const char*)(Ahi + (size_t)ga1c * K + lseg0 * 8);
    const char* pB0 = (const char*)(Bhi_g + (size_t)gb0c * K + lseg0 * 8);
    const char* pB1 = (const char*)(Bhi_g + (size_t)gb1c * K + lseg0 * 8);
    ptrdiff_t dAlo = (const char*)Alo - (const char*)Ahi;
    ptrdiff_t dBlo = (const char*)Blo_g - (const char*)Bhi_g;

    uint32_t aA[2][4], aB[2][4];
    {
        int rbase = wm * 64 + (lane & 15);
        int kseg = (lane >> 4) & 1;
#pragma unroll
        for (int ti = 0; ti < 4; ti++) {
            int rr = rbase + ti * 16;
            uint32_t off = (uint32_t)(rr * 64 + ((kseg ^ ((rr >> 1) & 3)) << 4));
            aA[0][ti] = sbase + off;
            aA[1][ti] = sbase + 8192 + off;
        }
        int nbase = wn * 32 + (lane & 7);
        int ksegb = (lane >> 3) & 1;
#pragma unroll
        for (int tj = 0; tj < 4; tj++) {
            int rr = nbase + tj * 8;
            uint32_t off = (uint32_t)(rr * 64 + ((ksegb ^ ((rr >> 1) & 3)) << 4));
            aB[0][tj] = sbase + 16384 + off;
            aB[1][tj] = sbase + 24576 + off;
        }
    }

    auto issue = [&](int st, int kc) {
        uint32_t sb = sbase + (uint32_t)(st * STAGE_BYTES);
        size_t ko = (size_t)kc * 64;
        cpasync16(sb + d0,         pA0 + ko,        pa0);
        cpasync16(sb + d1,         pA1 + ko,        pa1);
        cpasync16(sb + 8192 + d0,  pA0 + ko + dAlo, pa0);
        cpasync16(sb + 8192 + d1,  pA1 + ko + dAlo, pa1);
        cpasync16(sb + 16384 + d0, pB0 + ko,        pb0);
        cpasync16(sb + 16384 + d1, pB1 + ko,        pb1);
        cpasync16(sb + 24576 + d0, pB0 + ko + dBlo, pb0);
        cpasync16(sb + 24576 + d1, pB1 + ko + dBlo, pb1);
        CP_COMMIT();
    };

    issue(0, 0);
    for (int kc = 0; kc < NCH; kc++) {
        if (kc + 1 < NCH) {
            __syncthreads();
            issue((kc + 1) & 1, kc + 1);
            CP_WAIT1();
        } else {
            CP_WAIT0();
        }
        __syncthreads();
        uint32_t so = (uint32_t)((kc & 1) * STAGE_BYTES);
#pragma unroll
        for (int ks = 0; ks < 2; ks++) {
            uint32_t xk = (uint32_t)(ks * 32);
            unsigned Ahr[4][4], Alr[4][4], Bhr[4][2], Blr[4][2];
#pragma unroll
            for (int ti = 0; ti < 4; ti++) {
                ldsm4(Ahr[ti], (aA[0][ti] + so) ^ xk);
                ldsm4(Alr[ti], (aA[1][ti] + so) ^ xk);
            }
#pragma unroll
            for (int tj = 0; tj < 4; tj++) {
                ldsm2(Bhr[tj], (aB[0][tj] + so) ^ xk);
                ldsm2(Blr[tj], (aB[1][tj] + so) ^ xk);
            }
#pragma unroll
            for (int ti = 0; ti < 4; ti++)
#pragma unroll
                for (int tj = 0; tj < 4; tj++) {
                    float* cc = acc[ti * 4 + tj];
                    mma_fp16(cc, Ahr[ti], Bhr[tj]);
                    mma_fp16(cc, Ahr[ti], Blr[tj]);
                    mma_fp16(cc, Alr[ti], Bhr[tj]);
                }
        }
    }

#pragma unroll
    for (int ti = 0; ti < 4; ti++) {
#pragma unroll
        for (int tj = 0; tj < 4; tj++) {
            const float* cc = acc[ti * 4 + tj];
            int rA = row0 + wm * 64 + ti * 16 + (lane >> 2);
            int cA = col0 + wn * 32 + tj * 8 + (lane & 3) * 2;
#pragma unroll
            for (int q = 0; q < 4; q++) {
                int r = rA + ((q >= 2) ? 8 : 0);
                int c = cA + (q & 1);
                if (r < M && c < Ncol) {
                    float v = cc[q] + bias[c];
                    if (RELU) v = fmaxf(v, 0.f);
                    if (SPLIT) {
                        __half h, l;
                        split2(v, h, l);
                        Chi[(size_t)r * Ncol + c] = h;
                        Clo[(size_t)r * Ncol + c] = l;
                    } else {
                        C[(size_t)r * Ncol + c] = v;
                    }
                }
            }
        }
    }
}

// ---------------- GAT score weight vectors: wv[k] = (W@a) factored ----------
// wv4[k] = { src_h0, src_h1, dst_h0, dst_h1 }, wv4[k][t]: h=t&1, a = (t>>1)?adst:asrc
__global__ void k_wvec(const float* __restrict__ W, const float* __restrict__ asrc,
                       const float* __restrict__ adst, float* __restrict__ wv) {
    int idx = blockIdx.x * blockDim.x + threadIdx.x;
    if (idx < 2048) {
        int k = idx >> 2, t = idx & 3;
        int h = t & 1;
        const float* a = ((t >> 1) ? adst : asrc) + h * 512;
        const float* wr = W + (size_t)k * 1024 + h * 512;
        float s = 0.f;
        for (int c = 0; c < 512; c++) s += wr[c] * a[c];
        wv[idx] = s;
    }
}

// ---------------- GAT attention logits from GEMM INPUT (X . wv) --------------
// Xf (fp32) if non-null, else reconstruct from Xh+Xl. Warp per node, K=512.
__global__ void k_gat_scores2(const float* __restrict__ Xf,
                              const __half* __restrict__ Xh, const __half* __restrict__ Xl,
                              const float* __restrict__ wv,
                              float* __restrict__ als, float* __restrict__ ald, int n) {
    int gw = (blockIdx.x * blockDim.x + threadIdx.x) >> 5;
    int lane = threadIdx.x & 31;
    if (gw >= n) return;
    const float4* wv4 = (const float4*)wv;
    float s0 = 0, s1 = 0, d0 = 0, d1 = 0;
    if (Xf) {
        const float* xr = Xf + (size_t)gw * 512;
        for (int k = lane; k < 512; k += 32) {
            float xv = xr[k];
            float4 w = wv4[k];
            s0 += xv * w.x; s1 += xv * w.y;
            d0 += xv * w.z; d1 += xv * w.w;
        }
    } else {
        const __half* xh = Xh + (size_t)gw * 512;
        const __half* xl = Xl + (size_t)gw * 512;
        for (int k = lane; k < 512; k += 32) {
            float xv = __half2float(xh[k]) + __half2float(xl[k]);
            float4 w = wv4[k];
            s0 += xv * w.x; s1 += xv * w.y;
            d0 += xv * w.z; d1 += xv * w.w;
        }
    }
    for (int o = 16; o > 0; o >>= 1) {
        s0 += __shfl_down_sync(0xffffffffu, s0, o);
        s1 += __shfl_down_sync(0xffffffffu, s1, o);
        d0 += __shfl_down_sync(0xffffffffu, d0, o);
        d1 += __shfl_down_sync(0xffffffffu, d1, o);
    }
    if (lane == 0) {
        als[2 * gw] = s0; als[2 * gw + 1] = s1;
        ald[2 * gw] = d0; ald[2 * gw + 1] = d1;
    }
}

// ---------------- GAT aggregation (smem alpha cache; float4 gather) ----------
__global__ __launch_bounds__(256)
void k_gat_agg(const float* __restrict__ hW, const float* __restrict__ als,
               const float* __restrict__ ald, const float* __restrict__ bias,
               const int* __restrict__ rowptr, const int* __restrict__ csrsrc,
               float* __restrict__ out, __half* __restrict__ ohi,
               __half* __restrict__ olo, int relu) {
    __shared__ float red[256];
    __shared__ float bc[4];
    __shared__ int   sidx[256];
    __shared__ float sa0[256], sa1[256];
    int n = blockIdx.x, tid = threadIdx.x;
    int e0 = rowptr[n], e1 = rowptr[n + 1];
    float ad0 = ald[2 * n], ad1 = ald[2 * n + 1];
    float es0 = leaky02(als[2 * n] + ad0);
    float es1 = leaky02(als[2 * n + 1] + ad1);
    float m0 = es0, m1 = es1;
    for (int k = e0 + tid; k < e1; k += 256) {
        int s = csrsrc[k];
        m0 = fmaxf(m0, leaky02(als[2 * s] + ad0));
        m1 = fmaxf(m1, leaky02(als[2 * s + 1] + ad1));
    }
    red[tid] = m0; __syncthreads();
    for (int o = 128; o > 0; o >>= 1) { if (tid < o) red[tid] = fmaxf(red[tid], red[tid + o]); __syncthreads(); }
    if (tid == 0) bc[0] = red[0];
    __syncthreads();
    red[tid] = m1; __syncthreads();
    for (int o = 128; o > 0; o >>= 1) { if (tid < o) red[tid] = fmaxf(red[tid], red[tid + o]); __syncthreads(); }
    if (tid == 0) bc[1] = red[0];
    __syncthreads();
    m0 = bc[0]; m1 = bc[1];
    float t0 = 0, t1 = 0;
    for (int k = e0 + tid; k < e1; k += 256) {
        int s = csrsrc[k];
        t0 += expf(leaky02(als[2 * s] + ad0) - m0);
        t1 += expf(leaky02(als[2 * s + 1] + ad1) - m1);
    }
    red[tid] = t0; __syncthreads();
    for (int o = 128; o > 0; o >>= 1) { if (tid < o) red[tid] += red[tid + o]; __syncthreads(); }
    if (tid == 0) bc[2] = red[0] + expf(es0 - m0);
    __syncthreads();
    red[tid] = t1; __syncthreads();
    for (int o = 128; o > 0; o >>= 1) { if (tid < o) red[tid] += red[tid + o]; __syncthreads(); }
    if (tid == 0) bc[3] = red[0] + expf(es1 - m1);
    __syncthreads();
    float inv0 = 1.f / (bc[2] + 1e-16f);
    float inv1 = 1.f / (bc[3] + 1e-16f);
    int fb = tid * 4;
    float4 acc4 = make_float4(0.f, 0.f, 0.f, 0.f);
    for (int base = e0; base < e1; base += 256) {
        int cnt = min(256, e1 - base);
        __syncthreads();
        for (int k = tid; k < cnt; k += 256) {
            int s = csrsrc[base + k];
            sidx[k] = s;
            sa0[k] = expf(leaky02(als[2 * s] + ad0) - m0) * inv0;
            sa1[k] = expf(leaky02(als[2 * s + 1] + ad1) - m1) * inv1;
        }
        __syncthreads();
        for (int k = 0; k < cnt; k++) {
            int s = sidx[k];
            float a = (fb < 512) ? sa0[k] : sa1[k];
            float4 hv = *(const float4*)(hW + (size_t)s * 1024 + fb);
            acc4.x += hv.x * a;
            acc4.y += hv.y * a;
            acc4.z += hv.z * a;
            acc4.w += hv.w * a;
        }
    }
    {   // self loop
        float a = (fb < 512) ? (expf(es0 - m0) * inv0) : (expf(es1 - m1) * inv1);
        float4 hv = *(const float4*)(hW + (size_t)n * 1024 + fb);
        acc4.x += hv.x * a;
        acc4.y += hv.y * a;
        acc4.z += hv.z * a;
        acc4.w += hv.w * a;
    }
    {
        float4 bv = *(const float4*)(bias + fb);
        float v0 = acc4.x + bv.x, v1 = acc4.y + bv.y;
        float v2 = acc4.z + bv.z, v3 = acc4.w + bv.w;
        if (relu) {
            v0 = fmaxf(v0, 0.f); v1 = fmaxf(v1, 0.f);
            v2 = fmaxf(v2, 0.f); v3 = fmaxf(v3, 0.f);
        }
        size_t ob = (size_t)n * 1024 + fb;
        if (out) *(float4*)(out + ob) = make_float4(v0, v1, v2, v3);
        if (ohi) {
            __half h0, l0, h1, l1, h2, l2, h3, l3;
            split2(v0, h0, l0); split2(v1, h1, l1);
            split2(v2, h2, l2); split2(v3, h3, l3);
            *(__half2*)(ohi + ob)     = __halves2half2(h0, h1);
            *(__half2*)(ohi + ob + 2) = __halves2half2(h2, h3);
            *(__half2*)(olo + ob)     = __halves2half2(l0, l1);
            *(__half2*)(olo + ob + 2) = __halves2half2(l2, l3);
        }
    }
}

// ---------------- GCN aggregation (F=512; float2 gather; optional split) -----
__global__ __launch_bounds__(256)
void k_gcn_agg(const float* __restrict__ h, const float* __restrict__ dinv,
               const float* __restrict__ bias, const int* __restrict__ rowptr,
               const int* __restrict__ csrsrc, float* __restrict__ out,
               __half* __restrict__ ohi, __half* __restrict__ olo, int relu) {
    int n = blockIdx.x, tid = threadIdx.x;
    int e0 = rowptr[n], e1 = rowptr[n + 1];
    float dn = dinv[n];
    int fb = tid * 2;
    float a0 = 0.f, a1 = 0.f;
    for (int k = e0; k < e1; k++) {
        int s = csrsrc[k];
        float w = dinv[s] * dn;
        float2 hv = *(const float2*)(h + (size_t)s * 512 + fb);
        a0 += hv.x * w;
        a1 += hv.y * w;
    }
    {
        float ws = dn * dn;
        float2 hv = *(const float2*)(h + (size_t)n * 512 + fb);
        a0 += hv.x * ws + bias[fb];
        a1 += hv.y * ws + bias[fb + 1];
    }
    if (relu) { a0 = fmaxf(a0, 0.f); a1 = fmaxf(a1, 0.f); }
    size_t ob = (size_t)n * 512 + fb;
    if (out) *(float2*)(out + ob) = make_float2(a0, a1);
    if (ohi) {
        __half h0, l0, h1, l1;
        split2(a0, h0, l0);
        split2(a1, h1, l1);
        *(__half2*)(ohi + ob) = __halves2half2(h0, h1);
        *(__half2*)(olo + ob) = __halves2half2(l0, l1);
    }
}

// ---------------- column means: two-phase deterministic reduction ------------
__global__ __launch_bounds__(1024)
void k_colmean_p(const float* __restrict__ x, float* __restrict__ part, int n) {
    __shared__ float sh[1024];
    int tid = threadIdx.x;
    int col = (tid & 31) + blockIdx.x * 32;
    int rl = tid >> 5;
    int slice = blockIdx.y;
    int r0 = slice * 1250;
    int r1 = min(n, r0 + 1250);
    float s = 0.f;
    for (int r = r0 + rl; r < r1; r += 32) s += x[(size_t)r * 1024 + col];
    sh[rl * 32 + (tid & 31)] = s;
    __syncthreads();
    for (int o = 16; o > 0; o >>= 1) {
        if (rl < o) sh[rl * 32 + (tid & 31)] += sh[(rl + o) * 32 + (tid & 31)];
        __syncthreads();
    }
    if (rl == 0) part[slice * 1024 + col] = sh[tid & 31];
}

__global__ void k_colmean_r(const float* __restrict__ part, float* __restrict__ mean, int n) {
    int c = blockIdx.x * blockDim.x + threadIdx.x;
    if (c < 1024) {
        float s = 0.f;
        for (int i = 0; i < 8; i++) s += part[i * 1024 + c];
        mean[c] = s * (1.f / (float)n);
    }
}

// ---------------- fused centered sqnorm + fp16 split (one pass) --------------
__global__ void k_sqsplit(const float* __restrict__ d, const float* __restrict__ mean,
                          float* __restrict__ sq, __half* __restrict__ hi,
                          __half* __restrict__ lo, int n) {
    int gw = (blockIdx.x * blockDim.x + threadIdx.x) >> 5;
    int lane = threadIdx.x & 31;
    if (gw >= n) return;
    const float* r = d + (size_t)gw * 1024;
    float s = 0.f;
    for (int c = lane; c < 1024; c += 32) {
        float v = r[c] - mean[c];
        s += v * v;
        __half h, l;
        split2(v, h, l);
        hi[(size_t)gw * 1024 + c] = h;
        lo[(size_t)gw * 1024 + c] = l;
    }
    for (int o = 16; o > 0; o >>= 1) s += __shfl_down_sync(0xffffffffu, s, o);
    if (lane == 0) sq[gw] = s;
}

// ---------------- pdist via fp16-split tensor-core GEMM ----------------
// 1D triangular grid; 2-stage cp.async; transpose-staged mirror.
__global__ __launch_bounds__(256, 2)
void k_pdist_tc(const __half* __restrict__ Xhi, const __half* __restrict__ Xlo,
                const float* __restrict__ sq, float* __restrict__ out, int n) {
    const int K = 1024, NCH = 32;
    int NB = (n + 127) >> 7;
    int total = NB * (NB + 1) / 2;
    int u = total - 1 - (int)blockIdx.x;
    int k9 = (int)((sqrtf(8.f * (float)u + 1.f) - 1.f) * 0.5f);
    while ((k9 + 1) * (k9 + 2) / 2 <= u) k9++;
    while (k9 * (k9 + 1) / 2 > u) k9--;
    int bi = NB - 1 - k9;
    int bj = NB - 1 - (u - k9 * (k9 + 1) / 2);

    extern __shared__ __align__(1024) char dsm[];
    float* T = (float*)dsm;
    const int TS = 132;

    int tid = threadIdx.x;
    int lane = tid & 31, warp = tid >> 5;
    int wm = warp >> 2, wn = warp & 3;
    int g = lane >> 2, c4 = lane & 3;
    int row0 = bi * 128, col0 = bj * 128;

    float acc[16][4] = {};

    int lrow0 = tid >> 2, lseg0 = tid & 3;
    int s0 = lseg0 ^ ((lrow0 >> 1) & 3);
    int s1 = lseg0 ^ (((lrow0 + 64) >> 1) & 3);
    uint32_t sbase = (uint32_t)__cvta_generic_to_shared(dsm);
    uint32_t d0 = (uint32_t)(lrow0 * 64 + s0 * 16);
    uint32_t d1 = (uint32_t)((lrow0 + 64) * 64 + s1 * 16);

    int ga0 = row0 + lrow0, ga1 = ga0 + 64;
    int gb0 = col0 + lrow0, gb1 = gb0 + 64;
    int pa0 = (ga0 < n) ? 16 : 0, pa1 = (ga1 < n) ? 16 : 0;
    int pb0 = (gb0 < n) ? 16 : 0, pb1 = (gb1 < n) ? 16 : 0;
    int ga0c = (ga0 < n) ? ga0 : 0, ga1c = (ga1 < n) ? ga1 : 0;
    int gb0c = (gb0 < n) ? gb0 : 0, gb1c = (gb1 < n) ? gb1 : 0;
    const char* pA0 = (const char*)(Xhi + (size_t)ga0c * K + lseg0 * 8);
    const char* pA1 = (const char*)(Xhi + (size_t)ga1c * K + lseg0 * 8);
    const char* pB0 = (const char*)(Xhi + (size_t)gb0c * K + lseg0 * 8);
    const char* pB1 = (const char*)(Xhi + (size_t)gb1c * K + lseg0 * 8);
    ptrdiff_t dLO = (const char*)Xlo - (const char*)Xhi;

    uint32_t aA[2][4], aB[2][4];
    {
        int rbase = wm * 64 + (lane & 15);
        int kseg = (lane >> 4) & 1;
#pragma unroll
        for (int ti = 0; ti < 4; ti++) {
            int rr = rbase + ti * 16;
            uint32_t off = (uint32_t)(rr * 64 + ((kseg ^ ((rr >> 1) & 3)) << 4));
            aA[0][ti] = sbase + off;
            aA[1][ti] = sbase + 8192 + off;
        }
        int nbase = wn * 32 + (lane & 7);
        int ksegb = (lane >> 3) & 1;
#pragma unroll
        for (int tj = 0; tj < 4; tj++) {
            int rr = nbase + tj * 8;
            uint32_t off = (uint32_t)(rr * 64 + ((ksegb ^ ((rr >> 1) & 3)) << 4));
            aB[0][tj] = sbase + 16384 + off;
            aB[1][tj] = sbase + 24576 + off;
        }
    }

    auto issue = [&](int st, int kc) {
        uint32_t sb = sbase + (uint32_t)(st * STAGE_BYTES);
        size_t ko = (size_t)kc * 64;
        cpasync16(sb + d0,         pA0 + ko,       pa0);
        cpasync16(sb + d1,         pA1 + ko,       pa1);
        cpasync16(sb + 8192 + d0,  pA0 + ko + dLO, pa0);
        cpasync16(sb + 8192 + d1,  pA1 + ko + dLO, pa1);
        cpasync16(sb + 16384 + d0, pB0 + ko,       pb0);
        cpasync16(sb + 16384 + d1, pB1 + ko,       pb1);
        cpasync16(sb + 24576 + d0, pB0 + ko + dLO, pb0);
        cpasync16(sb + 24576 + d1, pB1 + ko + dLO, pb1);
        CP_COMMIT();
    };

    issue(0, 0);
    for (int kc = 0; kc < NCH; kc++) {
        if (kc + 1 < NCH) {
            __syncthreads();
            issue((kc + 1) & 1, kc + 1);
            CP_WAIT1();
        } else {
            CP_WAIT0();
        }
        __syncthreads();
        uint32_t so = (uint32_t)((kc & 1) * STAGE_BYTES);
#pragma unroll
        for (int ks = 0; ks < 2; ks++) {
            uint32_t xk = (uint32_t)(ks * 32);
            unsigned Ahi4[4][4], Alo4[4][4], Bhi4[4][2], Blo4[4][2];
#pragma unroll
            for (int ti = 0; ti < 4; ti++) {
                ldsm4(Ahi4[ti], (aA[0][ti] + so) ^ xk);
                ldsm4(Alo4[ti], (aA[1][ti] + so) ^ xk);
            }
#pragma unroll
            for (int tj = 0; tj < 4; tj++) {
                ldsm2(Bhi4[tj], (aB[0][tj] + so) ^ xk);
                ldsm2(Blo4[tj], (aB[1][tj] + so) ^ xk);
            }
#pragma unroll
            for (int ti = 0; ti < 4; ti++)
#pragma unroll
                for (int tj = 0; tj < 4; tj++) {
                    float* cc = acc[ti * 4 + tj];
                    mma_fp16(cc, Ahi4[ti], Bhi4[tj]);
                    mma_fp16(cc, Ahi4[ti], Blo4[tj]);
                    mma_fp16(cc, Alo4[ti], Bhi4[tj]);
                }
        }
    }

    // epilogue pass 1: dot -> distance, direct tile written as float2
#pragma unroll
    for (int ti = 0; ti < 4; ti++) {
#pragma unroll
        for (int tj = 0; tj < 4; tj++) {
            float* cc = acc[ti * 4 + tj];
            int rA = row0 + wm * 64 + ti * 16 + g;
            int cA = col0 + wn * 32 + tj * 8 + c4 * 2;
#pragma unroll
            for (int q = 0; q < 4; q++) {
                int r = rA + ((q >= 2) ? 8 : 0);
                int c = cA + (q & 1);
                float d2 = ((r < n) ? sq[r] : 0.f) + ((c < n) ? sq[c] : 0.f) - 2.f * cc[q];
                cc[q] = (r == c) ? 0.f : sqrtf(fmaxf(d2, 0.f));
            }
            if (rA < n) {
                if (cA + 1 < n) *(float2*)(out + (size_t)rA * n + cA) = make_float2(cc[0], cc[1]);
                else if (cA < n) out[(size_t)rA * n + cA] = cc[0];
            }
            if (rA + 8 < n) {
                if (cA + 1 < n) *(float2*)(out + (size_t)(rA + 8) * n + cA) = make_float2(cc[2], cc[3]);
                else if (cA < n) out[(size_t)(rA + 8) * n + cA] = cc[2];
            }
        }
    }

    // epilogue pass 2: mirror via transpose staging (2 halves of 64 columns)
#pragma unroll
    for (int h = 0; h < 2; h++) {
        __syncthreads();
        if ((wn >> 1) == h) {
#pragma unroll
            for (int ti = 0; ti < 4; ti++) {
#pragma unroll
                for (int tj = 0; tj < 4; tj++) {
                    const float* cc = acc[ti * 4 + tj];
                    int rl = wm * 64 + ti * 16 + g;
                    int clb = (wn & 1) * 32 + tj * 8 + c4 * 2;
                    T[(clb + 0) * TS + rl]     = cc[0];
                    T[(clb + 1) * TS + rl]     = cc[1];
                    T[(clb + 0) * TS + rl + 8] = cc[2];
                    T[(clb + 1) * TS + rl + 8] = cc[3];
                }
            }
        }
        __syncthreads();
        int cbase = col0 + h * 64;
        for (int idx = tid; idx < 64 * 32; idx += 256) {
            int cl = idx >> 5, rs = (idx & 31) * 4;
            int gr = cbase + cl;
            if (gr >= n) continue;
            int gc = row0 + rs;
            if (gc + 3 < n) {
                *(float4*)(out + (size_t)gr * n + gc) = *(float4*)&T[cl * TS + rs];
            } else {
                for (int e = 0; e < 4; e++)
                    if (gc + e < n) out[(size_t)gr * n + gc + e] = T[cl * TS + rs + e];
            }
        }
    }
}

// ---------------- host ----------------
extern "C" void kernel_launch(void* const* d_in, const int* in_sizes, int n_in,
                              void* d_out, int out_size) {
    (void)in_sizes; (void)n_in; (void)out_size;
    const float* x          = (const float*)d_in[0];
    const int*   ei         = (const int*)  d_in[1];
    const float* enc_gat_W  = (const float*)d_in[2];
    const float* enc_asrc   = (const float*)d_in[3];
    const float* enc_adst   = (const float*)d_in[4];
    const float* enc_gat_b  = (const float*)d_in[5];
    const float* enc_gcn_W  = (const float*)d_in[6];
    const float* enc_gcn_b  = (const float*)d_in[7];
    const float* densea_W   = (const float*)d_in[8];
    const float* densea_b   = (const float*)d_in[9];
    const float* latent_W   = (const float*)d_in[10];
    const float* latent_b   = (const float*)d_in[11];
    const float* dec1_W     = (const float*)d_in[12];
    const float* dec1_b     = (const float*)d_in[13];
    const float* dec2_W     = (const float*)d_in[14];
    const float* dec2_b     = (const float*)d_in[15];
    const float* dec_gcn_W  = (const float*)d_in[16];
    const float* dec_gcn_b  = (const float*)d_in[17];
    const float* dec_gat_W  = (const float*)d_in[18];
    const float* dec_asrc   = (const float*)d_in[19];
    const float* dec_adst   = (const float*)d_in[20];
    const float* dec_gat_b  = (const float*)d_in[21];
    const int* srcp = ei;
    const int* dstp = ei + EE;

    float *hW, *dfin, *lin512, *h3, *z, *als, *ald, *sqv, *dinv, *meanp, *mpart, *wv, *zb;
    int *deg, *rowptr, *cursor, *csrsrc;
    __half *Xhi, *Xlo, *Yhi, *Ylo, *Wh, *Wl;
    cudaGetSymbolAddress((void**)&hW, g_hW);
    cudaGetSymbolAddress((void**)&dfin, g_dfin);
    cudaGetSymbolAddress((void**)&lin512, g_lin512);
    cudaGetSymbolAddress((void**)&h3, g_h3);
    cudaGetSymbolAddress((void**)&z, g_z);
    cudaGetSymbolAddress((void**)&als, g_als);
    cudaGetSymbolAddress((void**)&ald, g_ald);
    cudaGetSymbolAddress((void**)&sqv, g_sq);
    cudaGetSymbolAddress((void**)&dinv, g_dinv);
    cudaGetSymbolAddress((void**)&meanp, g_mean);
    cudaGetSymbolAddress((void**)&mpart, g_mpart);
    cudaGetSymbolAddress((void**)&wv, g_wv);
    cudaGetSymbolAddress((void**)&zb, g_zero_bias);
    cudaGetSymbolAddress((void**)&deg, g_deg);
    cudaGetSymbolAddress((void**)&rowptr, g_rowptr);
    cudaGetSymbolAddress((void**)&cursor, g_cursor);
    cudaGetSymbolAddress((void**)&csrsrc, g_csrsrc);
    cudaGetSymbolAddress((void**)&Xhi, g_Xhi);
    cudaGetSymbolAddress((void**)&Xlo, g_Xlo);
    cudaGetSymbolAddress((void**)&Yhi, g_Yhi);
    cudaGetSymbolAddress((void**)&Ylo, g_Ylo);
    cudaGetSymbolAddress((void**)&Wh, g_Wh);
    cudaGetSymbolAddress((void**)&Wl, g_Wl);

    const int TB = 256;
    const int DSM = 2 * STAGE_BYTES;   // 64KB per CTA

    cudaFuncSetAttribute(k_hgemm<false, false>, cudaFuncAttributeMaxDynamicSharedMemorySize, DSM);
    cudaFuncSetAttribute(k_hgemm<true, false>,  cudaFuncAttributeMaxDynamicSharedMemorySize, DSM);
    cudaFuncSetAttribute(k_hgemm<true, true>,   cudaFuncAttributeMaxDynamicSharedMemorySize, DSM);
    cudaFuncSetAttribute(k_pdist_tc,            cudaFuncAttributeMaxDynamicSharedMemorySize, DSM);

    // CSR by dst
    k_zero_int<<<(NN + TB - 1) / TB, TB>>>(deg, NN);
    k_count  <<<(EE + TB - 1) / TB, TB>>>(dstp, deg, EE);
    k_scan   <<<1, 1024>>>(deg, rowptr, cursor, dinv, NN);
    k_fill   <<<(EE + TB - 1) / TB, TB>>>(srcp, dstp, rowptr, cursor, csrsrc, EE);

    // Encoder GAT: scores factored through GEMM input (als = x . (W@a))
    k_split <<<(NN * 512 + TB - 1) / TB, TB>>>(x, Xhi, Xlo, NN * 512);
    k_wsplit<<<(512 * 1024 + TB - 1) / TB, TB>>>(enc_gat_W, Wh, Wl, 512, 1024);
    k_wvec  <<<8, 256>>>(enc_gat_W, enc_asrc, enc_adst, wv);
    k_gat_scores2<<<(NN * 32 + TB - 1) / TB, TB>>>(x, nullptr, nullptr, wv, als, ald, NN);
    k_hgemm<false, false><<<dim3(8, 79), TB, DSM>>>(Xhi, Xlo, Wh, Wl, zb, hW, nullptr, nullptr, NN, 1024, 512);
    k_gat_agg<<<NN, TB>>>(hW, als, ald, enc_gat_b, rowptr, csrsrc, nullptr, Xhi, Xlo, 1);

    // Encoder GCN: agg emits fused split
    k_wsplit<<<(1024 * 512 + TB - 1) / TB, TB>>>(enc_gcn_W, Wh, Wl, 1024, 512);
    k_hgemm<false, false><<<dim3(4, 79), TB, DSM>>>(Xhi, Xlo, Wh, Wl, zb, lin512, nullptr, nullptr, NN, 512, 1024);
    k_gcn_agg<<<NN, TB>>>(lin512, dinv, enc_gcn_b, rowptr, csrsrc, nullptr, Xhi, Xlo, 1);

    // densea (+bias+relu) -> fp32 h3
    k_wsplit<<<(512 * 128 + TB - 1) / TB, TB>>>(densea_W, Wh, Wl, 512, 128);
    k_hgemm<true, false><<<dim3(1, 79), TB, DSM>>>(Xhi, Xlo, Wh, Wl, densea_b, h3, nullptr, nullptr, NN, 128, 512);

    // latent (fp32), dec1 (fp32 compute, fused split output)
    k_sgemm<true, false, false><<<dim3(1, 79), TB>>>(h3, latent_W, latent_b, z, nullptr, nullptr, NN, 64, 128);
    k_sgemm<true, true, true><<<dim3(1, 79), TB>>>(z, dec1_W, dec1_b, nullptr, Xhi, Xlo, NN, 128, 64);

    // dec2 (+bias+relu) -> fused split into Y
    k_wsplit<<<(128 * 512 + TB - 1) / TB, TB>>>(dec2_W, Wh, Wl, 128, 512);
    k_hgemm<true, true><<<dim3(4, 79), TB, DSM>>>(Xhi, Xlo, Wh, Wl, dec2_b, nullptr, Yhi, Ylo, NN, 512, 128);

    // Decoder GCN: agg emits fused split (Xhi/Xlo = d3 split)
    k_wsplit<<<(512 * 512 + TB - 1) / TB, TB>>>(dec_gcn_W, Wh, Wl, 512, 512);
    k_hgemm<false, false><<<dim3(4, 79), TB, DSM>>>(Yhi, Ylo, Wh, Wl, zb, lin512, nullptr, nullptr, NN, 512, 512);
    k_gcn_agg<<<NN, TB>>>(lin512, dinv, dec_gcn_b, rowptr, csrsrc, nullptr, Xhi, Xlo, 1);

    // Decoder GAT (no relu): scores from d3 split (hi+lo reconstruction)
    k_wsplit<<<(512 * 1024 + TB - 1) / TB, TB>>>(dec_gat_W, Wh, Wl, 512, 1024);
    k_wvec  <<<8, 256>>>(dec_gat_W, dec_asrc, dec_adst, wv);
    k_gat_scores2<<<(NN * 32 + TB - 1) / TB, TB>>>(nullptr, Xhi, Xlo, wv, als, ald, NN);
    k_hgemm<false, false><<<dim3(8, 79), TB, DSM>>>(Xhi, Xlo, Wh, Wl, zb, hW, nullptr, nullptr, NN, 1024, 512);
    k_gat_agg<<<NN, TB>>>(hW, als, ald, dec_gat_b, rowptr, csrsrc, dfin, nullptr, nullptr, 0);

    // pdist: center + fused sqnorm/split + tensor cores (triangular grid)
    k_colmean_p<<<dim3(32, 8), 1024>>>(dfin, mpart, NN);
    k_colmean_r<<<4, 256>>>(mpart, meanp, NN);
    k_sqsplit<<<(NN * 32 + TB - 1) / TB, TB>>>(dfin, meanp, sqv, Xhi, Xlo, NN);
    {
        int NB = (NN + 127) / 128;
        k_pdist_tc<<<NB * (NB + 1) / 2, TB, DSM>>>(Xhi, Xlo, sqv, (float*)d_out, NN);
    }
}

// round 16
// speedup vs baseline: 1.0504x; 1.0504x over previous
#include <cuda_runtime.h>
#include <cuda_fp16.h>
#include <math.h>
#include <stdint.h>

// Problem constants (fixed by the dataset).
#define NN 10000
#define EE 160000

// ---------------- device scratch (no allocations allowed) ----------------
__device__ __align__(256) float g_hW   [NN * 1024];
__device__ __align__(256) float g_dfin [NN * 1024];
__device__ __align__(256) float g_lin512[NN * 512];
__device__ __align__(256) float g_h3   [NN * 128];
__device__ __align__(256) float g_z    [NN * 64];
__device__ __align__(256) float g_als  [NN * 2];
__device__ __align__(256) float g_ald  [NN * 2];
__device__ __align__(256) float g_sq   [NN];
__device__ __align__(256) float g_dinv [NN];
__device__ __align__(256) float g_mean [1024];
__device__ __align__(256) float g_mpart[8 * 1024];
__device__ __align__(256) int   g_deg  [NN];
__device__ __align__(256) int   g_rowptr[NN + 1];
__device__ __align__(256) int   g_cursor[NN];
__device__ __align__(256) int   g_csrsrc[EE];
// fp16 2-term splits (primary + secondary to break aliasing in dec chain)
__device__ __align__(256) __half g_Xhi[NN * 1024];
__device__ __align__(256) __half g_Xlo[NN * 1024];
__device__ __align__(256) __half g_Yhi[NN * 512];
__device__ __align__(256) __half g_Ylo[NN * 512];
// fp16 2-term split of transposed weights (max 1024x512)
__device__ __align__(256) __half g_Wh[1 << 20];
__device__ __align__(256) __half g_Wl[1 << 20];

__device__ float g_zero_bias[1024];   // zero-initialized (bias-less layers)

__device__ __forceinline__ float leaky02(float x) { return x > 0.f ? x : 0.2f * x; }

__device__ __forceinline__ void split2(float v, __half& h, __half& l) {
    h = __float2half_rn(v);
    l = __float2half_rn(v - __half2float(h));
}

// ---------------- graph build ----------------
__global__ void k_zero_int(int* p, int n) {
    int i = blockIdx.x * blockDim.x + threadIdx.x;
    if (i < n) p[i] = 0;
}

__global__ void k_count(const int* __restrict__ dst, int* __restrict__ deg, int e) {
    int i = blockIdx.x * blockDim.x + threadIdx.x;
    if (i < e) atomicAdd(&deg[dst[i]], 1);
}

__global__ void k_scan(const int* __restrict__ deg, int* __restrict__ rowptr,
                       int* __restrict__ cursor, float* __restrict__ dinv, int n) {
    __shared__ int sh[1024];
    __shared__ int carry;
    int tid = threadIdx.x;
    if (tid == 0) carry = 0;
    __syncthreads();
    for (int base = 0; base < n; base += 1024) {
        int i = base + tid;
        int v = (i < n) ? deg[i] : 0;
        sh[tid] = v;
        __syncthreads();
        for (int off = 1; off < 1024; off <<= 1) {
            int t = (tid >= off) ? sh[tid - off] : 0;
            __syncthreads();
            sh[tid] += t;
            __syncthreads();
        }
        if (i < n) {
            rowptr[i] = carry + sh[tid] - v;   // exclusive
            cursor[i] = 0;
            dinv[i] = rsqrtf((float)(v + 1));
        }
        __syncthreads();
        if (tid == 0) carry += sh[1023];
        __syncthreads();
    }
    if (tid == 0) rowptr[n] = carry;
}

__global__ void k_fill(const int* __restrict__ src, const int* __restrict__ dst,
                       const int* __restrict__ rowptr, int* __restrict__ cursor,
                       int* __restrict__ csrsrc, int e) {
    int i = blockIdx.x * blockDim.x + threadIdx.x;
    if (i < e) {
        int d = dst[i];
        int p = atomicAdd(&cursor[d], 1);
        csrsrc[rowptr[d] + p] = src[i];
    }
}

// ---------------- fp32 GEMM (tiny layers; optional fp16-split output) --------
template <bool BIAS, bool RELU, bool SPLIT>
__global__ __launch_bounds__(256)
void k_sgemm(const float* __restrict__ A, const float* __restrict__ B,
             const float* __restrict__ bias, float* __restrict__ C,
             __half* __restrict__ Chi, __half* __restrict__ Clo,
             int M, int Ncol, int K) {
    const int BM = 128, BN = 128, BK = 8;
    __shared__ float As[BK][BM];
    __shared__ float Bs[BK][BN];
    int tid = threadIdx.x;
    int row0 = blockIdx.y * BM, col0 = blockIdx.x * BN;
    int tx = tid % 16, ty = tid / 16;
    float acc[8][8] = {};
    int aRow = tid >> 1, aCol = (tid & 1) * 4;
    int bRow = tid >> 5, bCol = (tid & 31) * 4;
    for (int k0 = 0; k0 < K; k0 += BK) {
        float4 av = make_float4(0, 0, 0, 0);
        if (row0 + aRow < M)
            av = *(const float4*)(A + (size_t)(row0 + aRow) * K + k0 + aCol);
        As[aCol + 0][aRow] = av.x; As[aCol + 1][aRow] = av.y;
        As[aCol + 2][aRow] = av.z; As[aCol + 3][aRow] = av.w;
        float4 bv = make_float4(0, 0, 0, 0);
        if (col0 + bCol < Ncol)
            bv = *(const float4*)(B + (size_t)(k0 + bRow) * Ncol + col0 + bCol);
        *(float4*)&Bs[bRow][bCol] = bv;
        __syncthreads();
#pragma unroll
        for (int k = 0; k < BK; k++) {
            float ar[8], br[8];
            *(float4*)ar       = *(float4*)&As[k][ty * 8];
            *(float4*)(ar + 4) = *(float4*)&As[k][ty * 8 + 4];
            *(float4*)br       = *(float4*)&Bs[k][tx * 8];
            *(float4*)(br + 4) = *(float4*)&Bs[k][tx * 8 + 4];
#pragma unroll
            for (int i = 0; i < 8; i++)
#pragma unroll
                for (int j = 0; j < 8; j++)
                    acc[i][j] = fmaf(ar[i], br[j], acc[i][j]);
        }
        __syncthreads();
    }
#pragma unroll
    for (int i = 0; i < 8; i++) {
        int r = row0 + ty * 8 + i;
        if (r >= M) continue;
#pragma unroll
        for (int j = 0; j < 8; j++) {
            int c = col0 + tx * 8 + j;
            if (c >= Ncol) continue;
            float v = acc[i][j];
            if (BIAS) v += bias[c];
            if (RELU) v = fmaxf(v, 0.f);
            if (SPLIT) {
                __half h, l;
                split2(v, h, l);
                Chi[(size_t)r * Ncol + c] = h;
                Clo[(size_t)r * Ncol + c] = l;
            } else {
                C[(size_t)r * Ncol + c] = v;
            }
        }
    }
}

// ---------------- fp16 2-term splits ----------------
__global__ void k_split(const float* __restrict__ x, __half* __restrict__ hi,
                        __half* __restrict__ lo, int n) {
    int i = blockIdx.x * blockDim.x + threadIdx.x;
    if (i < n) {
        __half h, l;
        split2(x[i], h, l);
        hi[i] = h; lo[i] = l;
    }
}

// W[K][N] row-major -> Wt_hi/lo[N][K] (transposed) fp16 split
__global__ void k_wsplit(const float* __restrict__ W, __half* __restrict__ hi,
                         __half* __restrict__ lo, int Kd, int Nd) {
    int i = blockIdx.x * blockDim.x + threadIdx.x;
    if (i < Kd * Nd) {
        int nr = i / Kd, kr = i % Kd;
        __half h, l;
        split2(W[(size_t)kr * Nd + nr], h, l);
        hi[i] = h; lo[i] = l;
    }
}

// ---------------- shared mma/ldmatrix/cp.async helpers ----------------
__device__ __forceinline__ void mma_fp16(float* c, const unsigned* a, const unsigned* b) {
    asm volatile(
        "mma.sync.aligned.m16n8k16.row.col.f32.f16.f16.f32 "
        "{%0,%1,%2,%3}, {%4,%5,%6,%7}, {%8,%9}, {%0,%1,%2,%3};\n"
        : "+f"(c[0]), "+f"(c[1]), "+f"(c[2]), "+f"(c[3])
        : "r"(a[0]), "r"(a[1]), "r"(a[2]), "r"(a[3]), "r"(b[0]), "r"(b[1]));
}

__device__ __forceinline__ void ldsm4(unsigned* r, uint32_t addr) {
    asm volatile("ldmatrix.sync.aligned.m8n8.x4.shared.b16 {%0,%1,%2,%3}, [%4];"
                 : "=r"(r[0]), "=r"(r[1]), "=r"(r[2]), "=r"(r[3]) : "r"(addr));
}
__device__ __forceinline__ void ldsm2(unsigned* r, uint32_t addr) {
    asm volatile("ldmatrix.sync.aligned.m8n8.x2.shared.b16 {%0,%1}, [%2];"
                 : "=r"(r[0]), "=r"(r[1]) : "r"(addr));
}

// .cg: bypass L1 (streamed once, no reuse)
__device__ __forceinline__ void cpasync16(uint32_t dst, const void* src, int srcbytes) {
    asm volatile("cp.async.cg.shared.global [%0], [%1], 16, %2;"
                 :: "r"(dst), "l"(src), "r"(srcbytes) : "memory");
}
#define CP_COMMIT() asm volatile("cp.async.commit_group;" ::: "memory")
#define CP_WAIT1()  asm volatile("cp.async.wait_group 1;" ::: "memory")
#define CP_WAIT0()  asm volatile("cp.async.wait_group 0;" ::: "memory")

#define STAGE_BYTES 32768

// ---------------- fp16-split dense GEMM: C = A @ Wt^T (+bias)(+relu) ----------
template <bool RELU, bool SPLIT>
__global__ __launch_bounds__(256, 2)
void k_hgemm(const __half* __restrict__ Ahi, const __half* __restrict__ Alo,
             const __half* __restrict__ Bhi_g, const __half* __restrict__ Blo_g,
             const float* __restrict__ bias, float* __restrict__ C,
             __half* __restrict__ Chi, __half* __restrict__ Clo,
             int M, int Ncol, int K) {
    int bi = blockIdx.y, bj = blockIdx.x;
    const int KC = 32;
    int NCH = K / KC;
    extern __shared__ __align__(1024) char dsm[];
    int tid = threadIdx.x;
    int lane = tid & 31, warp = tid >> 5;
    int wm = warp >> 2, wn = warp & 3;
    int row0 = bi * 128, col0 = bj * 128;

    float acc[16][4] = {};

    int lrow0 = tid >> 2, lseg0 = tid & 3;
    int s0 = lseg0 ^ ((lrow0 >> 1) & 3);
    int s1 = lseg0 ^ (((lrow0 + 64) >> 1) & 3);
    uint32_t sbase = (uint32_t)__cvta_generic_to_shared(dsm);
    uint32_t d0 = (uint32_t)(lrow0 * 64 + s0 * 16);
    uint32_t d1 = (uint32_t)((lrow0 + 64) * 64 + s1 * 16);

    int ga0 = row0 + lrow0, ga1 = ga0 + 64;
    int gb0 = col0 + lrow0, gb1 = gb0 + 64;
    int pa0 = (ga0 < M) ? 16 : 0, pa1 = (ga1 < M) ? 16 : 0;
    int pb0 = (gb0 < Ncol) ? 16 : 0, pb1 = (gb1 < Ncol) ? 16 : 0;
    int ga0c = (ga0 < M) ? ga0 : 0, ga1c = (ga1 < M) ? ga1 : 0;
    int gb0c = (gb0 < Ncol) ? gb0 : 0, gb1c = (gb1 < Ncol) ? gb1 : 0;
    const char* pA0 = (const char*)(Ahi + (size_t)ga0c * K + lseg0 * 8);
    const char* pA1 = (const char*)(Ahi + (size_t)ga1c * K + lseg0 * 8);
    const char* pB0 = (const char*)(Bhi_g + (size_t)gb0c * K + lseg0 * 8);
    const char* pB1 = (const char*)(Bhi_g + (size_t)gb1c * K + lseg0 * 8);
    ptrdiff_t dAlo = (const char*)Alo - (const char*)Ahi;
    ptrdiff_t dBlo = (const char*)Blo_g - (const char*)Bhi_g;

    uint32_t aA[2][4], aB[2][4];
    {
        int rbase = wm * 64 + (lane & 15);
        int kseg = (lane >> 4) & 1;
#pragma unroll
        for (int ti = 0; ti < 4; ti++) {
            int rr = rbase + ti * 16;
            uint32_t off = (uint32_t)(rr * 64 + ((kseg ^ ((rr >> 1) & 3)) << 4));
            aA[0][ti] = sbase + off;
            aA[1][ti] = sbase + 8192 + off;
        }
        int nbase = wn * 32 + (lane & 7);
        int ksegb = (lane >> 3) & 1;
#pragma unroll
        for (int tj = 0; tj < 4; tj++) {
            int rr = nbase + tj * 8;
            uint32_t off = (uint32_t)(rr * 64 + ((ksegb ^ ((rr >> 1) & 3)) << 4));
            aB[0][tj] = sbase + 16384 + off;
            aB[1][tj] = sbase + 24576 + off;
        }
    }

    auto issue = [&](int st, int kc) {
        uint32_t sb = sbase + (uint32_t)(st * STAGE_BYTES);
        size_t ko = (size_t)kc * 64;
        cpasync16(sb + d0,         pA0 + ko,        pa0);
        cpasync16(sb + d1,         pA1 + ko,        pa1);
        cpasync16(sb + 8192 + d0,  pA0 + ko + dAlo, pa0);
        cpasync16(sb + 8192 + d1,  pA1 + ko + dAlo, pa1);
        cpasync16(sb + 16384 + d0, pB0 + ko,        pb0);
        cpasync16(sb + 16384 + d1, pB1 + ko,        pb1);
        cpasync16(sb + 24576 + d0, pB0 + ko + dBlo, pb0);
        cpasync16(sb + 24576 + d1, pB1 + ko + dBlo, pb1);
        CP_COMMIT();
    };

    issue(0, 0);
    for (int kc = 0; kc < NCH; kc++) {
        if (kc + 1 < NCH) {
            __syncthreads();
            issue((kc + 1) & 1, kc + 1);
            CP_WAIT1();
        } else {
            CP_WAIT0();
        }
        __syncthreads();
        uint32_t so = (uint32_t)((kc & 1) * STAGE_BYTES);
#pragma unroll
        for (int ks = 0; ks < 2; ks++) {
            uint32_t xk = (uint32_t)(ks * 32);
            unsigned Ahr[4][4], Alr[4][4], Bhr[4][2], Blr[4][2];
#pragma unroll
            for (int ti = 0; ti < 4; ti++) {
                ldsm4(Ahr[ti], (aA[0][ti] + so) ^ xk);
                ldsm4(Alr[ti], (aA[1][ti] + so) ^ xk);
            }
#pragma unroll
            for (int tj = 0; tj < 4; tj++) {
                ldsm2(Bhr[tj], (aB[0][tj] + so) ^ xk);
                ldsm2(Blr[tj], (aB[1][tj] + so) ^ xk);
            }
#pragma unroll
            for (int ti = 0; ti < 4; ti++)
#pragma unroll
                for (int tj = 0; tj < 4; tj++) {
                    float* cc = acc[ti * 4 + tj];
                    mma_fp16(cc, Ahr[ti], Bhr[tj]);
                    mma_fp16(cc, Ahr[ti], Blr[tj]);
                    mma_fp16(cc, Alr[ti], Bhr[tj]);
                }
        }
    }

#pragma unroll
    for (int ti = 0; ti < 4; ti++) {
#pragma unroll
        for (int tj = 0; tj < 4; tj++) {
            const float* cc = acc[ti * 4 + tj];
            int rA = row0 + wm * 64 + ti * 16 + (lane >> 2);
            int cA = col0 + wn * 32 + tj * 8 + (lane & 3) * 2;
#pragma unroll
            for (int q = 0; q < 4; q++) {
                int r = rA + ((q >= 2) ? 8 : 0);
                int c = cA + (q & 1);
                if (r < M && c < Ncol) {
                    float v = cc[q] + bias[c];
                    if (RELU) v = fmaxf(v, 0.f);
                    if (SPLIT) {
                        __half h, l;
                        split2(v, h, l);
                        Chi[(size_t)r * Ncol + c] = h;
                        Clo[(size_t)r * Ncol + c] = l;
                    } else {
                        C[(size_t)r * Ncol + c] = v;
                    }
                }
            }
        }
    }
}

// ---------------- GAT attention logits ----------------
__global__ void k_gat_scores(const float* __restrict__ hW, const float* __restrict__ asrc,
                             const float* __restrict__ adst, float* __restrict__ als,
                             float* __restrict__ ald, int n) {
    int gw = (blockIdx.x * blockDim.x + threadIdx.x) >> 5;
    int lane = threadIdx.x & 31;
    if (gw >= n) return;
    const float* hr = hW + (size_t)gw * 1024;
    float s0 = 0, s1 = 0, d0 = 0, d1 = 0;
    for (int c = lane; c < 512; c += 32) {
        float h0 = hr[c], h1 = hr[512 + c];
        s0 += h0 * asrc[c];        d0 += h0 * adst[c];
        s1 += h1 * asrc[512 + c];  d1 += h1 * adst[512 + c];
    }
    for (int o = 16; o > 0; o >>= 1) {
        s0 += __shfl_down_sync(0xffffffffu, s0, o);
        s1 += __shfl_down_sync(0xffffffffu, s1, o);
        d0 += __shfl_down_sync(0xffffffffu, d0, o);
        d1 += __shfl_down_sync(0xffffffffu, d1, o);
    }
    if (lane == 0) {
        als[2 * gw] = s0; als[2 * gw + 1] = s1;
        ald[2 * gw] = d0; ald[2 * gw + 1] = d1;
    }
}

// ---------------- GAT aggregation (smem alpha cache; float4 gather;
//                  fused pairwise reduction ladders) ----------
__global__ __launch_bounds__(256)
void k_gat_agg(const float* __restrict__ hW, const float* __restrict__ als,
               const float* __restrict__ ald, const float* __restrict__ bias,
               const int* __restrict__ rowptr, const int* __restrict__ csrsrc,
               float* __restrict__ out, __half* __restrict__ ohi,
               __half* __restrict__ olo, int relu) {
    __shared__ float redA[256];
    __shared__ float redB[256];
    __shared__ float bc[4];
    __shared__ int   sidx[256];
    __shared__ float sa0[256], sa1[256];
    int n = blockIdx.x, tid = threadIdx.x;
    int e0 = rowptr[n], e1 = rowptr[n + 1];
    float ad0 = ald[2 * n], ad1 = ald[2 * n + 1];
    float es0 = leaky02(als[2 * n] + ad0);
    float es1 = leaky02(als[2 * n + 1] + ad1);
    float m0 = es0, m1 = es1;
    for (int k = e0 + tid; k < e1; k += 256) {
        int s = csrsrc[k];
        m0 = fmaxf(m0, leaky02(als[2 * s] + ad0));
        m1 = fmaxf(m1, leaky02(als[2 * s + 1] + ad1));
    }
    // fused max ladders (each array's combine order identical to a solo tree)
    redA[tid] = m0; redB[tid] = m1; __syncthreads();
    for (int o = 128; o > 0; o >>= 1) {
        if (tid < o) {
            redA[tid] = fmaxf(redA[tid], redA[tid + o]);
            redB[tid] = fmaxf(redB[tid], redB[tid + o]);
        }
        __syncthreads();
    }
    if (tid == 0) { bc[0] = redA[0]; bc[1] = redB[0]; }
    __syncthreads();
    m0 = bc[0]; m1 = bc[1];
    float t0 = 0, t1 = 0;
    for (int k = e0 + tid; k < e1; k += 256) {
        int s = csrsrc[k];
        t0 += expf(leaky02(als[2 * s] + ad0) - m0);
        t1 += expf(leaky02(als[2 * s + 1] + ad1) - m1);
    }
    // fused sum ladders
    redA[tid] = t0; redB[tid] = t1; __syncthreads();
    for (int o = 128; o > 0; o >>= 1) {
        if (tid < o) {
            redA[tid] += redA[tid + o];
            redB[tid] += redB[tid + o];
        }
        __syncthreads();
    }
    if (tid == 0) {
        bc[2] = redA[0] + expf(es0 - m0);
        bc[3] = redB[0] + expf(es1 - m1);
    }
    __syncthreads();
    float inv0 = 1.f / (bc[2] + 1e-16f);
    float inv1 = 1.f / (bc[3] + 1e-16f);
    int fb = tid * 4;
    float4 acc4 = make_float4(0.f, 0.f, 0.f, 0.f);
    for (int base = e0; base < e1; base += 256) {
        int cnt = min(256, e1 - base);
        __syncthreads();
        for (int k = tid; k < cnt; k += 256) {
            int s = csrsrc[base + k];
            sidx[k] = s;
            sa0[k] = expf(leaky02(als[2 * s] + ad0) - m0) * inv0;
            sa1[k] = expf(leaky02(als[2 * s + 1] + ad1) - m1) * inv1;
        }
        __syncthreads();
        for (int k = 0; k < cnt; k++) {
            int s = sidx[k];
            float a = (fb < 512) ? sa0[k] : sa1[k];
            float4 hv = *(const float4*)(hW + (size_t)s * 1024 + fb);
            acc4.x += hv.x * a;
            acc4.y += hv.y * a;
            acc4.z += hv.z * a;
            acc4.w += hv.w * a;
        }
    }
    {   // self loop
        float a = (fb < 512) ? (expf(es0 - m0) * inv0) : (expf(es1 - m1) * inv1);
        float4 hv = *(const float4*)(hW + (size_t)n * 1024 + fb);
        acc4.x += hv.x * a;
        acc4.y += hv.y * a;
        acc4.z += hv.z * a;
        acc4.w += hv.w * a;
    }
    {
        float4 bv = *(const float4*)(bias + fb);
        float v0 = acc4.x + bv.x, v1 = acc4.y + bv.y;
        float v2 = acc4.z + bv.z, v3 = acc4.w + bv.w;
        if (relu) {
            v0 = fmaxf(v0, 0.f); v1 = fmaxf(v1, 0.f);
            v2 = fmaxf(v2, 0.f); v3 = fmaxf(v3, 0.f);
        }
        size_t ob = (size_t)n * 1024 + fb;
        if (out) *(float4*)(out + ob) = make_float4(v0, v1, v2, v3);
        if (ohi) {
            __half h0, l0, h1, l1, h2, l2, h3, l3;
            split2(v0, h0, l0); split2(v1, h1, l1);
            split2(v2, h2, l2); split2(v3, h3, l3);
            *(__half2*)(ohi + ob)     = __halves2half2(h0, h1);
            *(__half2*)(ohi + ob + 2) = __halves2half2(h2, h3);
            *(__half2*)(olo + ob)     = __halves2half2(l0, l1);
            *(__half2*)(olo + ob + 2) = __halves2half2(l2, l3);
        }
    }
}

// ---------------- GCN aggregation (F=512; float2 gather; optional split) -----
__global__ __launch_bounds__(256)
void k_gcn_agg(const float* __restrict__ h, const float* __restrict__ dinv,
               const float* __restrict__ bias, const int* __restrict__ rowptr,
               const int* __restrict__ csrsrc, float* __restrict__ out,
               __half* __restrict__ ohi, __half* __restrict__ olo, int relu) {
    int n = blockIdx.x, tid = threadIdx.x;
    int e0 = rowptr[n], e1 = rowptr[n + 1];
    float dn = dinv[n];
    int fb = tid * 2;
    float a0 = 0.f, a1 = 0.f;
    for (int k = e0; k < e1; k++) {
        int s = csrsrc[k];
        float w = dinv[s] * dn;
        float2 hv = *(const float2*)(h + (size_t)s * 512 + fb);
        a0 += hv.x * w;
        a1 += hv.y * w;
    }
    {
        float ws = dn * dn;
        float2 hv = *(const float2*)(h + (size_t)n * 512 + fb);
        a0 += hv.x * ws + bias[fb];
        a1 += hv.y * ws + bias[fb + 1];
    }
    if (relu) { a0 = fmaxf(a0, 0.f); a1 = fmaxf(a1, 0.f); }
    size_t ob = (size_t)n * 512 + fb;
    if (out) *(float2*)(out + ob) = make_float2(a0, a1);
    if (ohi) {
        __half h0, l0, h1, l1;
        split2(a0, h0, l0);
        split2(a1, h1, l1);
        *(__half2*)(ohi + ob) = __halves2half2(h0, h1);
        *(__half2*)(olo + ob) = __halves2half2(l0, l1);
    }
}

// ---------------- column means: two-phase deterministic reduction ------------
__global__ __launch_bounds__(1024)
void k_colmean_p(const float* __restrict__ x, float* __restrict__ part, int n) {
    __shared__ float sh[1024];
    int tid = threadIdx.x;
    int col = (tid & 31) + blockIdx.x * 32;
    int rl = tid >> 5;
    int slice = blockIdx.y;
    int r0 = slice * 1250;
    int r1 = min(n, r0 + 1250);
    float s = 0.f;
    for (int r = r0 + rl; r < r1; r += 32) s += x[(size_t)r * 1024 + col];
    sh[rl * 32 + (tid & 31)] = s;
    __syncthreads();
    for (int o = 16; o > 0; o >>= 1) {
        if (rl < o) sh[rl * 32 + (tid & 31)] += sh[(rl + o) * 32 + (tid & 31)];
        __syncthreads();
    }
    if (rl == 0) part[slice * 1024 + col] = sh[tid & 31];
}

__global__ void k_colmean_r(const float* __restrict__ part, float* __restrict__ mean, int n) {
    int c = blockIdx.x * blockDim.x + threadIdx.x;
    if (c < 1024) {
        float s = 0.f;
        for (int i = 0; i < 8; i++) s += part[i * 1024 + c];
        mean[c] = s * (1.f / (float)n);
    }
}

// ---------------- fused centered sqnorm + fp16 split (one pass) --------------
__global__ void k_sqsplit(const float* __restrict__ d, const float* __restrict__ mean,
                          float* __restrict__ sq, __half* __restrict__ hi,
                          __half* __restrict__ lo, int n) {
    int gw = (blockIdx.x * blockDim.x + threadIdx.x) >> 5;
    int lane = threadIdx.x & 31;
    if (gw >= n) return;
    const float* r = d + (size_t)gw * 1024;
    float s = 0.f;
    for (int c = lane; c < 1024; c += 32) {
        float v = r[c] - mean[c];
        s += v * v;
        __half h, l;
        split2(v, h, l);
        hi[(size_t)gw * 1024 + c] = h;
        lo[(size_t)gw * 1024 + c] = l;
    }
    for (int o = 16; o > 0; o >>= 1) s += __shfl_down_sync(0xffffffffu, s, o);
    if (lane == 0) sq[gw] = s;
}

// ---------------- pdist via fp16-split tensor-core GEMM ----------------
// 1D triangular grid; 2-stage cp.async; transpose-staged mirror.
__global__ __launch_bounds__(256, 2)
void k_pdist_tc(const __half* __restrict__ Xhi, const __half* __restrict__ Xlo,
                const float* __restrict__ sq, float* __restrict__ out, int n) {
    const int K = 1024, NCH = 32;
    int NB = (n + 127) >> 7;
    int total = NB * (NB + 1) / 2;
    int u = total - 1 - (int)blockIdx.x;
    int k9 = (int)((sqrtf(8.f * (float)u + 1.f) - 1.f) * 0.5f);
    while ((k9 + 1) * (k9 + 2) / 2 <= u) k9++;
    while (k9 * (k9 + 1) / 2 > u) k9--;
    int bi = NB - 1 - k9;
    int bj = NB - 1 - (u - k9 * (k9 + 1) / 2);

    extern __shared__ __align__(1024) char dsm[];
    float* T = (float*)dsm;
    const int TS = 132;

    int tid = threadIdx.x;
    int lane = tid & 31, warp = tid >> 5;
    int wm = warp >> 2, wn = warp & 3;
    int g = lane >> 2, c4 = lane & 3;
    int row0 = bi * 128, col0 = bj * 128;

    float acc[16][4] = {};

    int lrow0 = tid >> 2, lseg0 = tid & 3;
    int s0 = lseg0 ^ ((lrow0 >> 1) & 3);
    int s1 = lseg0 ^ (((lrow0 + 64) >> 1) & 3);
    uint32_t sbase = (uint32_t)__cvta_generic_to_shared(dsm);
    uint32_t d0 = (uint32_t)(lrow0 * 64 + s0 * 16);
    uint32_t d1 = (uint32_t)((lrow0 + 64) * 64 + s1 * 16);

    int ga0 = row0 + lrow0, ga1 = ga0 + 64;
    int gb0 = col0 + lrow0, gb1 = gb0 + 64;
    int pa0 = (ga0 < n) ? 16 : 0, pa1 = (ga1 < n) ? 16 : 0;
    int pb0 = (gb0 < n) ? 16 : 0, pb1 = (gb1 < n) ? 16 : 0;
    int ga0c = (ga0 < n) ? ga0 : 0, ga1c = (ga1 < n) ? ga1 : 0;
    int gb0c = (gb0 < n) ? gb0 : 0, gb1c = (gb1 < n) ? gb1 : 0;
    const char* pA0 = (const char*)(Xhi + (size_t)ga0c * K + lseg0 * 8);
    const char* pA1 = (const char*)(Xhi + (size_t)ga1c * K + lseg0 * 8);
    const char* pB0 = (const char*)(Xhi + (size_t)gb0c * K + lseg0 * 8);
    const char* pB1 = (const char*)(Xhi + (size_t)gb1c * K + lseg0 * 8);
    ptrdiff_t dLO = (const char*)Xlo - (const char*)Xhi;

    uint32_t aA[2][4], aB[2][4];
    {
        int rbase = wm * 64 + (lane & 15);
        int kseg = (lane >> 4) & 1;
#pragma unroll
        for (int ti = 0; ti < 4; ti++) {
            int rr = rbase + ti * 16;
            uint32_t off = (uint32_t)(rr * 64 + ((kseg ^ ((rr >> 1) & 3)) << 4));
            aA[0][ti] = sbase + off;
            aA[1][ti] = sbase + 8192 + off;
        }
        int nbase = wn * 32 + (lane & 7);
        int ksegb = (lane >> 3) & 1;
#pragma unroll
        for (int tj = 0; tj < 4; tj++) {
            int rr = nbase + tj * 8;
            uint32_t off = (uint32_t)(rr * 64 + ((ksegb ^ ((rr >> 1) & 3)) << 4));
            aB[0][tj] = sbase + 16384 + off;
            aB[1][tj] = sbase + 24576 + off;
        }
    }

    auto issue = [&](int st, int kc) {
        uint32_t sb = sbase + (uint32_t)(st * STAGE_BYTES);
        size_t ko = (size_t)kc * 64;
        cpasync16(sb + d0,         pA0 + ko,       pa0);
        cpasync16(sb + d1,         pA1 + ko,       pa1);
        cpasync16(sb + 8192 + d0,  pA0 + ko + dLO, pa0);
        cpasync16(sb + 8192 + d1,  pA1 + ko + dLO, pa1);
        cpasync16(sb + 16384 + d0, pB0 + ko,       pb0);
        cpasync16(sb + 16384 + d1, pB1 + ko,       pb1);
        cpasync16(sb + 24576 + d0, pB0 + ko + dLO, pb0);
        cpasync16(sb + 24576 + d1, pB1 + ko + dLO, pb1);
        CP_COMMIT();
    };

    issue(0, 0);
    for (int kc = 0; kc < NCH; kc++) {
        if (kc + 1 < NCH) {
            __syncthreads();
            issue((kc + 1) & 1, kc + 1);
            CP_WAIT1();
        } else {
            CP_WAIT0();
        }
        __syncthreads();
        uint32_t so = (uint32_t)((kc & 1) * STAGE_BYTES);
#pragma unroll
        for (int ks = 0; ks < 2; ks++) {
            uint32_t xk = (uint32_t)(ks * 32);
            unsigned Ahi4[4][4], Alo4[4][4], Bhi4[4][2], Blo4[4][2];
#pragma unroll
            for (int ti = 0; ti < 4; ti++) {
                ldsm4(Ahi4[ti], (aA[0][ti] + so) ^ xk);
                ldsm4(Alo4[ti], (aA[1][ti] + so) ^ xk);
            }
#pragma unroll
            for (int tj = 0; tj < 4; tj++) {
                ldsm2(Bhi4[tj], (aB[0][tj] + so) ^ xk);
                ldsm2(Blo4[tj], (aB[1][tj] + so) ^ xk);
            }
#pragma unroll
            for (int ti = 0; ti < 4; ti++)
#pragma unroll
                for (int tj = 0; tj < 4; tj++) {
                    float* cc = acc[ti * 4 + tj];
                    mma_fp16(cc, Ahi4[ti], Bhi4[tj]);
                    mma_fp16(cc, Ahi4[ti], Blo4[tj]);
                    mma_fp16(cc, Alo4[ti], Bhi4[tj]);
                }
        }
    }

    // epilogue pass 1: dot -> distance, direct tile written as float2
#pragma unroll
    for (int ti = 0; ti < 4; ti++) {
#pragma unroll
        for (int tj = 0; tj < 4; tj++) {
            float* cc = acc[ti * 4 + tj];
            int rA = row0 + wm * 64 + ti * 16 + g;
            int cA = col0 + wn * 32 + tj * 8 + c4 * 2;
#pragma unroll
            for (int q = 0; q < 4; q++) {
                int r = rA + ((q >= 2) ? 8 : 0);
                int c = cA + (q & 1);
                float d2 = ((r < n) ? sq[r] : 0.f) + ((c < n) ? sq[c] : 0.f) - 2.f * cc[q];
                cc[q] = (r == c) ? 0.f : sqrtf(fmaxf(d2, 0.f));
            }
            if (rA < n) {
                if (cA + 1 < n) *(float2*)(out + (size_t)rA * n + cA) = make_float2(cc[0], cc[1]);
                else if (cA < n) out[(size_t)rA * n + cA] = cc[0];
            }
            if (rA + 8 < n) {
                if (cA + 1 < n) *(float2*)(out + (size_t)(rA + 8) * n + cA) = make_float2(cc[2], cc[3]);
                else if (cA < n) out[(size_t)(rA + 8) * n + cA] = cc[2];
            }
        }
    }

    // epilogue pass 2: mirror via transpose staging (2 halves of 64 columns)
#pragma unroll
    for (int h = 0; h < 2; h++) {
        __syncthreads();
        if ((wn >> 1) == h) {
#pragma unroll
            for (int ti = 0; ti < 4; ti++) {
#pragma unroll
                for (int tj = 0; tj < 4; tj++) {
                    const float* cc = acc[ti * 4 + tj];
                    int rl = wm * 64 + ti * 16 + g;
                    int clb = (wn & 1) * 32 + tj * 8 + c4 * 2;
                    T[(clb + 0) * TS + rl]     = cc[0];
                    T[(clb + 1) * TS + rl]     = cc[1];
                    T[(clb + 0) * TS + rl + 8] = cc[2];
                    T[(clb + 1) * TS + rl + 8] = cc[3];
                }
            }
        }
        __syncthreads();
        int cbase = col0 + h * 64;
        for (int idx = tid; idx < 64 * 32; idx += 256) {
            int cl = idx >> 5, rs = (idx & 31) * 4;
            int gr = cbase + cl;
            if (gr >= n) continue;
            int gc = row0 + rs;
            if (gc + 3 < n) {
                *(float4*)(out + (size_t)gr * n + gc) = *(float4*)&T[cl * TS + rs];
            } else {
                for (int e = 0; e < 4; e++)
                    if (gc + e < n) out[(size_t)gr * n + gc + e] = T[cl * TS + rs + e];
            }
        }
    }
}

// ---------------- host ----------------
extern "C" void kernel_launch(void* const* d_in, const int* in_sizes, int n_in,
                              void* d_out, int out_size) {
    (void)in_sizes; (void)n_in; (void)out_size;
    const float* x          = (const float*)d_in[0];
    const int*   ei         = (const int*)  d_in[1];
    const float* enc_gat_W  = (const float*)d_in[2];
    const float* enc_asrc   = (const float*)d_in[3];
    const float* enc_adst   = (const float*)d_in[4];
    const float* enc_gat_b  = (const float*)d_in[5];
    const float* enc_gcn_W  = (const float*)d_in[6];
    const float* enc_gcn_b  = (const float*)d_in[7];
    const float* densea_W   = (const float*)d_in[8];
    const float* densea_b   = (const float*)d_in[9];
    const float* latent_W   = (const float*)d_in[10];
    const float* latent_b   = (const float*)d_in[11];
    const float* dec1_W     = (const float*)d_in[12];
    const float* dec1_b     = (const float*)d_in[13];
    const float* dec2_W     = (const float*)d_in[14];
    const float* dec2_b     = (const float*)d_in[15];
    const float* dec_gcn_W  = (const float*)d_in[16];
    const float* dec_gcn_b  = (const float*)d_in[17];
    const float* dec_gat_W  = (const float*)d_in[18];
    const float* dec_asrc   = (const float*)d_in[19];
    const float* dec_adst   = (const float*)d_in[20];
    const float* dec_gat_b  = (const float*)d_in[21];
    const int* srcp = ei;
    const int* dstp = ei + EE;

    float *hW, *dfin, *lin512, *h3, *z, *als, *ald, *sqv, *dinv, *meanp, *mpart, *zb;
    int *deg, *rowptr, *cursor, *csrsrc;
    __half *Xhi, *Xlo, *Yhi, *Ylo, *Wh, *Wl;
    cudaGetSymbolAddress((void**)&hW, g_hW);
    cudaGetSymbolAddress((void**)&dfin, g_dfin);
    cudaGetSymbolAddress((void**)&lin512, g_lin512);
    cudaGetSymbolAddress((void**)&h3, g_h3);
    cudaGetSymbolAddress((void**)&z, g_z);
    cudaGetSymbolAddress((void**)&als, g_als);
    cudaGetSymbolAddress((void**)&ald, g_ald);
    cudaGetSymbolAddress((void**)&sqv, g_sq);
    cudaGetSymbolAddress((void**)&dinv, g_dinv);
    cudaGetSymbolAddress((void**)&meanp, g_mean);
    cudaGetSymbolAddress((void**)&mpart, g_mpart);
    cudaGetSymbolAddress((void**)&zb, g_zero_bias);
    cudaGetSymbolAddress((void**)&deg, g_deg);
    cudaGetSymbolAddress((void**)&rowptr, g_rowptr);
    cudaGetSymbolAddress((void**)&cursor, g_cursor);
    cudaGetSymbolAddress((void**)&csrsrc, g_csrsrc);
    cudaGetSymbolAddress((void**)&Xhi, g_Xhi);
    cudaGetSymbolAddress((void**)&Xlo, g_Xlo);
    cudaGetSymbolAddress((void**)&Yhi, g_Yhi);
    cudaGetSymbolAddress((void**)&Ylo, g_Ylo);
    cudaGetSymbolAddress((void**)&Wh, g_Wh);
    cudaGetSymbolAddress((void**)&Wl, g_Wl);

    const int TB = 256;
    const int DSM = 2 * STAGE_BYTES;   // 64KB per CTA

    cudaFuncSetAttribute(k_hgemm<false, false>, cudaFuncAttributeMaxDynamicSharedMemorySize, DSM);
    cudaFuncSetAttribute(k_hgemm<true, false>,  cudaFuncAttributeMaxDynamicSharedMemorySize, DSM);
    cudaFuncSetAttribute(k_hgemm<true, true>,   cudaFuncAttributeMaxDynamicSharedMemorySize, DSM);
    cudaFuncSetAttribute(k_pdist_tc,            cudaFuncAttributeMaxDynamicSharedMemorySize, DSM);

    // CSR by dst
    k_zero_int<<<(NN + TB - 1) / TB, TB>>>(deg, NN);
    k_count  <<<(EE + TB - 1) / TB, TB>>>(dstp, deg, EE);
    k_scan   <<<1, 1024>>>(deg, rowptr, cursor, dinv, NN);
    k_fill   <<<(EE + TB - 1) / TB, TB>>>(srcp, dstp, rowptr, cursor, csrsrc, EE);

    // Encoder GAT: hW = x @ W; agg emits fused fp16 split
    k_split <<<(NN * 512 + TB - 1) / TB, TB>>>(x, Xhi, Xlo, NN * 512);
    k_wsplit<<<(512 * 1024 + TB - 1) / TB, TB>>>(enc_gat_W, Wh, Wl, 512, 1024);
    k_hgemm<false, false><<<dim3(8, 79), TB, DSM>>>(Xhi, Xlo, Wh, Wl, zb, hW, nullptr, nullptr, NN, 1024, 512);
    k_gat_scores<<<(NN * 32 + TB - 1) / TB, TB>>>(hW, enc_asrc, enc_adst, als, ald, NN);
    k_gat_agg<<<NN, TB>>>(hW, als, ald, enc_gat_b, rowptr, csrsrc, nullptr, Xhi, Xlo, 1);

    // Encoder GCN: agg emits fused split
    k_wsplit<<<(1024 * 512 + TB - 1) / TB, TB>>>(enc_gcn_W, Wh, Wl, 1024, 512);
    k_hgemm<false, false><<<dim3(4, 79), TB, DSM>>>(Xhi, Xlo, Wh, Wl, zb, lin512, nullptr, nullptr, NN, 512, 1024);
    k_gcn_agg<<<NN, TB>>>(lin512, dinv, enc_gcn_b, rowptr, csrsrc, nullptr, Xhi, Xlo, 1);

    // densea (+bias+relu) -> fp32 h3
    k_wsplit<<<(512 * 128 + TB - 1) / TB, TB>>>(densea_W, Wh, Wl, 512, 128);
    k_hgemm<true, false><<<dim3(1, 79), TB, DSM>>>(Xhi, Xlo, Wh, Wl, densea_b, h3, nullptr, nullptr, NN, 128, 512);

    // latent (fp32), dec1 (fp32 compute, fused split output)
    k_sgemm<true, false, false><<<dim3(1, 79), TB>>>(h3, latent_W, latent_b, z, nullptr, nullptr, NN, 64, 128);
    k_sgemm<true, true, true><<<dim3(1, 79), TB>>>(z, dec1_W, dec1_b, nullptr, Xhi, Xlo, NN, 128, 64);

    // dec2 (+bias+relu) -> fused split into Y
    k_wsplit<<<(128 * 512 + TB - 1) / TB, TB>>>(dec2_W, Wh, Wl, 128, 512);
    k_hgemm<true, true><<<dim3(4, 79), TB, DSM>>>(Xhi, Xlo, Wh, Wl, dec2_b, nullptr, Yhi, Ylo, NN, 512, 128);

    // Decoder GCN: agg emits fused split
    k_wsplit<<<(512 * 512 + TB - 1) / TB, TB>>>(dec_gcn_W, Wh, Wl, 512, 512);
    k_hgemm<false, false><<<dim3(4, 79), TB, DSM>>>(Yhi, Ylo, Wh, Wl, zb, lin512, nullptr, nullptr, NN, 512, 512);
    k_gcn_agg<<<NN, TB>>>(lin512, dinv, dec_gcn_b, rowptr, csrsrc, nullptr, Xhi, Xlo, 1);

    // Decoder GAT (no relu) -> fp32 dfin
    k_wsplit<<<(512 * 1024 + TB - 1) / TB, TB>>>(dec_gat_W, Wh, Wl, 512, 1024);
    k_hgemm<false, false><<<dim3(8, 79), TB, DSM>>>(Xhi, Xlo, Wh, Wl, zb, hW, nullptr, nullptr, NN, 1024, 512);
    k_gat_scores<<<(NN * 32 + TB - 1) / TB, TB>>>(hW, dec_asrc, dec_adst, als, ald, NN);
    k_gat_agg<<<NN, TB>>>(hW, als, ald, dec_gat_b, rowptr, csrsrc, dfin, nullptr, nullptr, 0);

    // pdist: center + fused sqnorm/split + tensor cores (triangular grid)
    k_colmean_p<<<dim3(32, 8), 1024>>>(dfin, mpart, NN);
    k_colmean_r<<<4, 256>>>(mpart, meanp, NN);
    k_sqsplit<<<(NN * 32 + TB - 1) / TB, TB>>>(dfin, meanp, sqv, Xhi, Xlo, NN);
    {
        int NB = (NN + 127) / 128;
        k_pdist_tc<<<NB * (NB + 1) / 2, TB, DSM>>>(Xhi, Xlo, sqv, (float*)d_out, NN);
    }
}